// round 12
// baseline (speedup 1.0000x reference)
#include <cuda_runtime.h>
#include <math.h>
#include <float.h>

// ---------------------------------------------------------------------------
// EceLabelShift: equal-mass-bin ECE with label-shift weighting.
//   conf = max softmax prob  (= 1/sum(exp(l - max)))
//   edges = equal-mass quantiles of conf_target (exact order statistics via
//           2-level radix histogram on the positive-float bit pattern)
//   per-bin: weighted source accuracy -> cond_expect; sum (conf_t - ce)^2
// R11: entire tail fused into ONE persistent kernel (148 co-resident blocks,
//      software grid barriers) -> 4 graph nodes instead of 11.
// ---------------------------------------------------------------------------

#define NC      100
#define NBINS   15
#define HSIZE   (1 << 18)            // conf in (0,1] -> bits>>12 < 0x40000
#define CHUNK   1024
#define NCHUNK  (HSIZE / CHUNK)      // 256
#define NRANK   32                   // 16 edges x (i, i+1) rank pairs
#define NMAX    500000
#define TB      148                  // tail blocks (<= SM count: all co-resident)
#define TT      256                  // tail threads per block

struct ZeroBlock {
    unsigned hist[HSIZE];
    unsigned subhist[NRANK * 4096];
    double   wnum[NBINS];
    double   total;
    unsigned cnt[NBINS];
};
__device__ ZeroBlock gz;

__device__ float    g_conf_t[NMAX];
__device__ float    g_conf_s[NMAX];
__device__ float    g_wper[NMAX];
__device__ unsigned g_csum[NCHUNK];
__device__ int      g_rankBin[NRANK];
__device__ unsigned g_rankBase[NRANK];
__device__ float    g_srt[NRANK];
__device__ float    g_edges[16];
__device__ float    g_ce[NBINS];
__device__ unsigned char g_cntok[NBINS];
__device__ int      g_lab64;
__device__ unsigned g_sync_cnt;      // monotonic grid-barrier ticket (never reset)

// --------------------------- grid barrier -----------------------------------
__device__ __forceinline__ void grid_sync() {
    __syncthreads();
    if (threadIdx.x == 0) {
        __threadfence();                                   // release my writes
        unsigned ticket = atomicAdd(&g_sync_cnt, 1u);
        unsigned target = (ticket / TB + 1u) * TB;
        unsigned v;
        do {
            asm volatile("ld.acquire.gpu.u32 %0, [%1];"
                         : "=r"(v) : "l"(&g_sync_cnt));
        } while (v < target);
    }
    __syncthreads();
}

// rank (0-indexed order statistic) needed for edge pair t: (i, i+1), clamped.
__device__ __forceinline__ long long rank_for(int t, int nt) {
    int k = t >> 1;
    double xq = (double)k * (double)nt / 15.0;
    long long i = (long long)floor(xq);
    if (i > (long long)nt - 1) i = (long long)nt - 1;
    long long r = i + (t & 1);
    if (r > (long long)nt - 1) r = (long long)nt - 1;
    return r;
}

// Inclusive block scan over 256 threads (8 warps). All 256 threads must call.
__device__ __forceinline__ unsigned blockScan256(unsigned v, unsigned* sh) {
    int tid = threadIdx.x, lane = tid & 31, w = tid >> 5;
    unsigned sc = v;
#pragma unroll
    for (int o = 1; o < 32; o <<= 1) {
        unsigned u = __shfl_up_sync(0xffffffffu, sc, o);
        if (lane >= o) sc += u;
    }
    if (lane == 31) sh[w] = sc;
    __syncthreads();
    if (tid < 8) {
        unsigned t = sh[tid];
#pragma unroll
        for (int o = 1; o < 8; o <<= 1) {
            unsigned u = __shfl_up_sync(0xffu, t, o);
            if (tid >= o) t += u;
        }
        sh[tid] = t;
    }
    __syncthreads();
    return sc + (w ? sh[w - 1] : 0u);
}

// Block reduce-sum over 256 threads; result valid on tid 0.
__device__ __forceinline__ unsigned blockRed256(unsigned v, unsigned* sh) {
    int tid = threadIdx.x;
#pragma unroll
    for (int o = 16; o; o >>= 1) v += __shfl_xor_sync(0xffffffffu, v, o);
    if ((tid & 31) == 0) sh[tid >> 5] = v;
    __syncthreads();
    unsigned r = 0;
    if (tid < 8) {
        r = sh[tid];
#pragma unroll
        for (int o = 4; o; o >>= 1) r += __shfl_xor_sync(0xffu, r, o);
    }
    __syncthreads();
    return r;
}

// Detect labels dtype: int64 => odd 32-bit words of first 64 entries are 0.
__global__ void k_detect(const unsigned* __restrict__ lab) {
    int t = threadIdx.x;                       // 32 threads
    unsigned v = lab[2 * t + 1] | lab[2 * t + 65];
    unsigned mask = __ballot_sync(0xffffffffu, v != 0u);
    if (t == 0) g_lab64 = (mask == 0u) ? 1 : 0;
}

// Fused conf pass: one warp per row for target (rows [0,nt)) and source rows.
__global__ void k_conf(const float* __restrict__ lg_t, const float* __restrict__ lg_s,
                       const void* __restrict__ labels, const float* __restrict__ wt,
                       int nt, int ns) {
    int gw   = (blockIdx.x * blockDim.x + threadIdx.x) >> 5;
    int lane = threadIdx.x & 31;
    if (gw >= nt + ns) return;
    bool isT = gw < nt;
    int row  = isT ? gw : gw - nt;
    const float* base = isT ? lg_t : lg_s;
    const float4* p = (const float4*)(base + (size_t)row * NC);  // 400B rows: 16B aligned
    float4 v;
    if (lane < 25) v = p[lane];
    else           v = make_float4(-FLT_MAX, -FLT_MAX, -FLT_MAX, -FLT_MAX);

    float m = fmaxf(fmaxf(v.x, v.y), fmaxf(v.z, v.w));
#pragma unroll
    for (int o = 16; o; o >>= 1) m = fmaxf(m, __shfl_xor_sync(0xffffffffu, m, o));

    float s = 0.0f;
    if (lane < 25)
        s = __expf(v.x - m) + __expf(v.y - m) + __expf(v.z - m) + __expf(v.w - m);
#pragma unroll
    for (int o = 16; o; o >>= 1) s += __shfl_xor_sync(0xffffffffu, s, o);

    if (isT) {
        if (lane == 0) {
            float c = 1.0f / s;
            g_conf_t[row] = c;
            atomicAdd(&gz.hist[__float_as_uint(c) >> 12], 1u);
        }
    } else {
        // argmax (first occurrence): smallest index whose value == m
        int loc = 127;
        if (lane < 25) {
            if (v.w == m) loc = 4 * lane + 3;
            if (v.z == m) loc = 4 * lane + 2;
            if (v.y == m) loc = 4 * lane + 1;
            if (v.x == m) loc = 4 * lane;
        }
        unsigned mask = __ballot_sync(0xffffffffu, loc < 127);
        int src = __ffs(mask) - 1;
        int bi  = __shfl_sync(0xffffffffu, loc, src);
        if (lane == 0) {
            g_conf_s[row] = 1.0f / s;
            long long lab = g_lab64 ? ((const long long*)labels)[row]
                                    : (long long)((const int*)labels)[row];
            g_wper[row] = (bi == (int)lab) ? wt[lab] : 0.0f;
        }
    }
}

// ---------------------------------------------------------------------------
// Persistent tail: csum -> rank -> refine -> select -> edges -> binacc -> ce
//                  -> diff -> final, all in one launch with grid barriers.
// ---------------------------------------------------------------------------
__global__ void __launch_bounds__(TT, 1) k_tail(float* __restrict__ out, int ns, int nt) {
    __shared__ unsigned s_cpref[NCHUNK + 1];
    __shared__ unsigned s_sh[32];
    __shared__ int      s_cIdx;
    __shared__ int      s_first;
    __shared__ float    s_e[16];
    __shared__ float    s_ce[NBINS];
    __shared__ unsigned char s_ok[NBINS];
    __shared__ float    s_wn[NBINS];
    __shared__ unsigned s_ct[NBINS];
    __shared__ int      s_bins[NRANK];
    __shared__ double   s_ws[8];

    const int tid = threadIdx.x;
    const int bid = blockIdx.x;
    const int gstride = TB * TT;
    const int gtid = bid * TT + tid;

    // ---- Phase 1: per-chunk sums of coarse histogram ----
    for (int c = bid; c < NCHUNK; c += TB) {
        unsigned s = 0;
        const unsigned* hp = &gz.hist[c * CHUNK + tid * 4];
#pragma unroll
        for (int j = 0; j < 4; j++) s += hp[j];
        unsigned tot = blockRed256(s, s_sh);
        if (tid == 0) g_csum[c] = tot;
    }
    grid_sync();

    // ---- Phase 2: rank location (blocks 0..31) ----
    if (bid < NRANK) {
        if (tid == 0) s_first = 1 << 30;
        if (tid < 32) {
            unsigned pre[8]; unsigned run = 0;
#pragma unroll
            for (int j = 0; j < 8; j++) { unsigned h = g_csum[tid * 8 + j]; pre[j] = run; run += h; }
            unsigned sc = run;
#pragma unroll
            for (int o = 1; o < 32; o <<= 1) {
                unsigned u = __shfl_up_sync(0xffffffffu, sc, o);
                if (tid >= o) sc += u;
            }
            unsigned excl = sc - run;
#pragma unroll
            for (int j = 0; j < 8; j++) s_cpref[tid * 8 + j] = excl + pre[j];
            if (tid == 31) s_cpref[NCHUNK] = excl + run;
        }
        __syncthreads();
        unsigned r = (unsigned)rank_for(bid, nt);
        if (s_cpref[tid] <= r && r < s_cpref[tid + 1]) s_cIdx = tid;
        __syncthreads();
        int c = s_cIdx;
        unsigned h[4], tsum = 0;
        const unsigned* hp = &gz.hist[c * CHUNK + tid * 4];
#pragma unroll
        for (int j = 0; j < 4; j++) { h[j] = hp[j]; tsum += h[j]; }
        unsigned incl = blockScan256(tsum, s_sh);
        unsigned cum = s_cpref[c] + incl - tsum;
        int found = -1; unsigned cc = cum;
#pragma unroll
        for (int j = 0; j < 4; j++) {
            if (found < 0 && cc + h[j] > r) found = tid * 4 + j;
            cc += h[j];
        }
        if (found >= 0) atomicMin(&s_first, found);
        __syncthreads();
        if (found == s_first && found >= 0) {
            g_rankBin[bid] = c * CHUNK + found;
            unsigned basecnt = cum;
            int jj = found - tid * 4;
            for (int j = 0; j < jj; j++) basecnt += h[j];
            g_rankBase[bid] = basecnt;
        }
    }
    grid_sync();

    // ---- Phase 3: refine sub-histograms (all blocks) ----
    if (tid < NRANK) s_bins[tid] = g_rankBin[tid];
    __syncthreads();
    {
        int bmin = 0x7fffffff, bmax = -1;
#pragma unroll
        for (int t = 0; t < NRANK; t++) {
            int b = s_bins[t];
            bmin = min(bmin, b); bmax = max(bmax, b);
        }
        for (int i = gtid; i < nt; i += gstride) {
            unsigned key = __float_as_uint(g_conf_t[i]);
            int bbin = (int)(key >> 12);
            if (bbin < bmin || bbin > bmax) continue;
            unsigned low = key & 4095u;
#pragma unroll
            for (int t = 0; t < NRANK; t++)
                if (s_bins[t] == bbin) atomicAdd(&gz.subhist[t * 4096 + low], 1u);
        }
    }
    grid_sync();

    // ---- Phase 4: select exact order statistics (blocks 0..31) ----
    if (bid < NRANK) {
        if (tid == 0) s_first = 1 << 30;
        __syncthreads();
        unsigned target = (unsigned)(rank_for(bid, nt) - (long long)g_rankBase[bid]);
        unsigned h[16], tsum = 0;
        const unsigned* hp = &gz.subhist[bid * 4096 + tid * 16];
#pragma unroll
        for (int j = 0; j < 16; j++) { h[j] = hp[j]; tsum += h[j]; }
        unsigned incl = blockScan256(tsum, s_sh);
        unsigned cc = incl - tsum;
        int found = -1;
#pragma unroll
        for (int j = 0; j < 16; j++) {
            if (found < 0 && cc + h[j] > target) found = tid * 16 + j;
            cc += h[j];
        }
        if (found >= 0) atomicMin(&s_first, found);
        __syncthreads();
        if (tid == 0)
            g_srt[bid] = __uint_as_float(((unsigned)g_rankBin[bid] << 12) | (unsigned)s_first);
    }
    grid_sync();

    // ---- Phase 5: edges (block 0) ----
    if (bid == 0 && tid < 16) {
        int k = tid; float e;
        if (k == 0)       e = g_srt[0];
        else if (k == 15) e = g_srt[31];
        else {
            double xq = (double)k * (double)nt / 15.0;
            long long i = (long long)floor(xq);
            double frac = xq - (double)i;
            double a = g_srt[2 * k], b2 = g_srt[2 * k + 1];
            e = (float)(a + frac * (b2 - a));
        }
        g_edges[k] = e;
    }
    grid_sync();

    // ---- Phase 6: bin accumulation (blocks <74 source, rest target) ----
    if (tid < 16)    s_e[tid] = g_edges[tid];
    if (tid < NBINS) { s_wn[tid] = 0.0f; s_ct[tid] = 0u; }
    __syncthreads();
    if (bid < TB / 2) {
        int stride = (TB / 2) * TT;
        for (int i = bid * TT + tid; i < ns; i += stride) {
            float w = g_wper[i];
            if (w != 0.0f) {
                float c = g_conf_s[i];
                if (c > s_e[0] && c <= s_e[15]) {
#pragma unroll
                    for (int b = 0; b < NBINS; b++)
                        if (c <= s_e[b + 1]) { atomicAdd(&s_wn[b], w); break; }
                }
            }
        }
    } else {
        int nb = TB - TB / 2;
        int stride = nb * TT;
        for (int i = (bid - TB / 2) * TT + tid; i < nt; i += stride) {
            float c = g_conf_t[i];
            if (c > s_e[0] && c <= s_e[15]) {
#pragma unroll
                for (int b = 0; b < NBINS; b++)
                    if (c <= s_e[b + 1]) { atomicAdd(&s_ct[b], 1u); break; }
            }
        }
    }
    __syncthreads();
    if (tid < NBINS) {
        if (s_wn[tid] != 0.0f) atomicAdd(&gz.wnum[tid], (double)s_wn[tid]);
        if (s_ct[tid])         atomicAdd(&gz.cnt[tid], s_ct[tid]);
    }
    grid_sync();

    // ---- Phase 7: cond_expect (block 0) ----
    if (bid == 0 && tid < NBINS) {
        long long ct = (long long)gz.cnt[tid];
        long long d  = ct - 1; if (d < 1) d = 1;
        double normal = (double)(nt - 1) / (double)ns;
        g_ce[tid]    = (float)(normal * gz.wnum[tid] / (double)d);
        g_cntok[tid] = (ct > 1) ? 1 : 0;
    }
    grid_sync();

    // ---- Phase 8: sum (conf_t - ce[bin])^2 (all blocks) ----
    if (tid < NBINS) { s_ce[tid] = g_ce[tid]; s_ok[tid] = g_cntok[tid]; }
    __syncthreads();
    {
        double local = 0.0;
        for (int i = gtid; i < nt; i += gstride) {
            float c = g_conf_t[i];
            if (c > s_e[0] && c <= s_e[15]) {
#pragma unroll
                for (int b = 0; b < NBINS; b++)
                    if (c <= s_e[b + 1]) {
                        if (s_ok[b]) { float d = c - s_ce[b]; local += (double)d * (double)d; }
                        break;
                    }
            }
        }
#pragma unroll
        for (int o = 16; o; o >>= 1) local += __shfl_down_sync(0xffffffffu, local, o);
        if ((tid & 31) == 0) s_ws[tid >> 5] = local;
        __syncthreads();
        if (tid < 8) {
            double v = s_ws[tid];
#pragma unroll
            for (int o = 4; o; o >>= 1) v += __shfl_down_sync(0xffu, v, o);
            if (tid == 0) atomicAdd(&gz.total, v);
        }
    }
    grid_sync();

    // ---- Phase 9: final ----
    if (bid == 0 && tid == 0) out[0] = (float)(gz.total / (double)nt);
}

extern "C" void kernel_launch(void* const* d_in, const int* in_sizes, int n_in,
                              void* d_out, int out_size) {
    const float* lg_s = (const float*)d_in[0];
    const void*  lab  = d_in[1];
    const float* lg_t = (const float*)d_in[2];
    const float* wt   = (const float*)d_in[3];
    int ns = in_sizes[0] / NC;
    int nt = in_sizes[2] / NC;

    void* zp = nullptr;
    cudaGetSymbolAddress(&zp, gz);
    cudaMemsetAsync(zp, 0, sizeof(ZeroBlock), 0);

    k_detect<<<1, 32>>>((const unsigned*)lab);

    const int WPB = 8;  // 8 warps/block, one warp per row
    int rows = nt + ns;
    int blocks = (rows + WPB - 1) / WPB;
    k_conf<<<blocks, 256>>>(lg_t, lg_s, lab, wt, nt, ns);

    k_tail<<<TB, TT>>>((float*)d_out, ns, nt);
    (void)n_in; (void)out_size;
}